// round 10
// baseline (speedup 1.0000x reference)
#include <cuda_runtime.h>
#include <cuda_bf16.h>

// WMAE: out = sum_{i,j} w[j] * |t1[i,j] - t2[i,j]| / n_sample
// t1, t2: (4194304, 3) fp32 row-major. w = {300, 1, 200}.
// HBM-bound streaming reduction: 100.66 MB read -> scalar.
//
// Coalescing: pure grid-stride over float4s (consecutive lanes ->
// consecutive 16B, one LDG.128 = 4 cache lines). Weight pattern of float4
// index k depends only on k%3 (4 == 1 mod 3); grid stride chosen % 3 == 0
// so each thread's weight vector is loop-invariant.

#define W0 300.0f
#define W1   1.0f
#define W2 200.0f

__global__ void wmae_zero_kernel(float* out) {
    out[0] = 0.0f;
}

__global__ void __launch_bounds__(256)
wmae_kernel(const float4* __restrict__ a4,
            const float4* __restrict__ b4,
            const float*  __restrict__ a,
            const float*  __restrict__ b,
            float* __restrict__ out,
            int n4, int n_total, float inv_n)
{
    const int tid    = blockIdx.x * blockDim.x + threadIdx.x;
    const int stride = gridDim.x * blockDim.x;   // launch guarantees stride % 3 == 0

    // Loop-invariant per-thread weight vector: element j of float4 k has
    // feature index (k + j) mod 3; k mod 3 == tid mod 3 for all iterations.
    const float w3[3] = {W0, W1, W2};
    const int r = tid % 3;
    const float wx = w3[r];
    const float wy = w3[(r + 1) % 3];
    const float wz = w3[(r + 2) % 3];
    const float ww = wx;

    float s0 = 0.0f, s1 = 0.0f, s2 = 0.0f, s3 = 0.0f;

    int k = tid;
    // Batched x4: 8 independent LDG.128 in flight per trip.
    for (; k + 3 * stride < n4; k += 4 * stride) {
        float4 a0 = a4[k];              float4 b0 = b4[k];
        float4 a1 = a4[k + stride];     float4 b1 = b4[k + stride];
        float4 a2 = a4[k + 2 * stride]; float4 b2 = b4[k + 2 * stride];
        float4 a3 = a4[k + 3 * stride]; float4 b3 = b4[k + 3 * stride];

        s0 += wx * fabsf(a0.x - b0.x) + wy * fabsf(a0.y - b0.y)
            + wz * fabsf(a0.z - b0.z) + ww * fabsf(a0.w - b0.w);
        s1 += wx * fabsf(a1.x - b1.x) + wy * fabsf(a1.y - b1.y)
            + wz * fabsf(a1.z - b1.z) + ww * fabsf(a1.w - b1.w);
        s2 += wx * fabsf(a2.x - b2.x) + wy * fabsf(a2.y - b2.y)
            + wz * fabsf(a2.z - b2.z) + ww * fabsf(a2.w - b2.w);
        s3 += wx * fabsf(a3.x - b3.x) + wy * fabsf(a3.y - b3.y)
            + wz * fabsf(a3.z - b3.z) + ww * fabsf(a3.w - b3.w);
    }
    // Remainder grid-stride iterations.
    for (; k < n4; k += stride) {
        float4 av = a4[k]; float4 bv = b4[k];
        s0 += wx * fabsf(av.x - bv.x) + wy * fabsf(av.y - bv.y)
            + wz * fabsf(av.z - bv.z) + ww * fabsf(av.w - bv.w);
    }

    float s = (s0 + s1) + (s2 + s3);

    // Scalar tail (n_total % 4 != 0) — empty for this shape, kept for safety.
    for (int i = n4 * 4 + tid; i < n_total; i += stride)
        s += w3[i % 3] * fabsf(a[i] - b[i]);

    // Warp reduction
    #pragma unroll
    for (int off = 16; off > 0; off >>= 1)
        s += __shfl_xor_sync(0xFFFFFFFFu, s, off);

    // Block reduction
    __shared__ float warp_sums[8];
    const int lane = threadIdx.x & 31;
    const int wid  = threadIdx.x >> 5;
    if (lane == 0) warp_sums[wid] = s;
    __syncthreads();

    if (wid == 0) {
        s = (lane < (blockDim.x >> 5)) ? warp_sums[lane] : 0.0f;
        #pragma unroll
        for (int off = 4; off > 0; off >>= 1)
            s += __shfl_xor_sync(0xFFFFFFFFu, s, off);
        if (lane == 0)
            atomicAdd(out, s * inv_n);
    }
}

extern "C" void kernel_launch(void* const* d_in, const int* in_sizes, int n_in,
                              void* d_out, int out_size)
{
    const float* t1 = (const float*)d_in[0];
    const float* t2 = (const float*)d_in[1];
    float* out = (float*)d_out;

    const int n_total  = in_sizes[0];          // 12,582,912
    const int n4       = n_total / 4;          // 3,145,728 float4s
    const int n_sample = n_total / 3;          // 4,194,304
    const float inv_n  = 1.0f / (float)n_sample;

    wmae_zero_kernel<<<1, 1>>>(out);

    const int threads = 256;
    // 1182 = 3 * 394: stride % 3 == 0 (required for loop-invariant weights),
    // ~8 blocks per SM on 148 SMs.
    int blocks = 1182;
    int needed = (n4 + threads - 1) / threads;
    if (needed < blocks) blocks = ((needed + 2) / 3) * 3;  // keep % 3 == 0
    if (blocks < 3) blocks = 3;

    wmae_kernel<<<blocks, threads>>>(
        (const float4*)t1, (const float4*)t2,
        t1, t2, out, n4, n_total, inv_n);
}

// round 11
// speedup vs baseline: 1.1600x; 1.1600x over previous
#include <cuda_runtime.h>
#include <cuda_bf16.h>
#include <cstdint>

// WMAE: out = sum_{i,j} w[j]*|t1[i,j]-t2[i,j]| / n_sample
// t1,t2: (4194304, 3) fp32. 100.66 MB read -> scalar. HBM-bound.
//
// Bulk-async (UBLKCP) 3-stage smem pipeline to escape the per-SM
// outstanding-LDG-miss limit that capped plain-LDG versions at ~67% DRAM.

#define W0 300.0f
#define W1   1.0f
#define W2 200.0f

#define THREADS       128
#define STAGES        3
#define CHUNK_BYTES   6144              // per tensor per stage
#define CHUNK_FLOATS  1536              // divisible by 3 -> weight phase 0
#define STAGE_BYTES   (2 * CHUNK_BYTES) // a-chunk + b-chunk

__global__ void wmae_zero_kernel(float* out) { out[0] = 0.0f; }

__device__ __forceinline__ uint32_t smem_u32(const void* p) {
    return (uint32_t)__cvta_generic_to_shared(p);
}
__device__ __forceinline__ void mbar_init(uint32_t a, uint32_t cnt) {
    asm volatile("mbarrier.init.shared.b64 [%0], %1;" :: "r"(a), "r"(cnt) : "memory");
}
__device__ __forceinline__ void mbar_expect_tx(uint32_t a, uint32_t bytes) {
    asm volatile("mbarrier.arrive.expect_tx.shared.b64 _, [%0], %1;"
                 :: "r"(a), "r"(bytes) : "memory");
}
__device__ __forceinline__ void bulk_g2s(uint32_t dst, const void* src,
                                         uint32_t bytes, uint32_t mbar) {
    asm volatile(
        "cp.async.bulk.shared::cta.global.mbarrier::complete_tx::bytes "
        "[%0], [%1], %2, [%3];"
        :: "r"(dst), "l"(src), "r"(bytes), "r"(mbar) : "memory");
}
__device__ __forceinline__ void mbar_wait(uint32_t a, uint32_t parity) {
    uint32_t done;
    asm volatile(
        "{\n\t.reg .pred p;\n\t"
        "mbarrier.try_wait.parity.acquire.cta.shared::cta.b64 p, [%1], %2;\n\t"
        "selp.b32 %0, 1, 0, p;\n\t}"
        : "=r"(done) : "r"(a), "r"(parity) : "memory");
    while (!done) {
        asm volatile(
            "{\n\t.reg .pred p;\n\t"
            "mbarrier.try_wait.parity.acquire.cta.shared::cta.b64 p, [%1], %2, 0x989680;\n\t"
            "selp.b32 %0, 1, 0, p;\n\t}"
            : "=r"(done) : "r"(a), "r"(parity) : "memory");
    }
}

__global__ void __launch_bounds__(THREADS)
wmae_kernel(const char* __restrict__ ga, const char* __restrict__ gb,
            const float* __restrict__ fa, const float* __restrict__ fb,
            float* __restrict__ out, int nchunks, int n_total, float inv_n)
{
    __shared__ __align__(128) char sm[STAGES * STAGE_BYTES];   // 36 KB
    __shared__ uint64_t mbar[STAGES];
    __shared__ float warp_sums[THREADS / 32];

    const int tid  = threadIdx.x;
    const int bid  = blockIdx.x;
    const int grid = gridDim.x;

    if (tid == 0) {
        #pragma unroll
        for (int s = 0; s < STAGES; s++) mbar_init(smem_u32(&mbar[s]), 1);
        asm volatile("fence.proxy.async.shared::cta;" ::: "memory");
    }
    __syncthreads();

    // Chunks assigned grid-stride: c_i = bid + i*grid
    const int myn = (bid < nchunks) ? (nchunks - bid + grid - 1) / grid : 0;

    // Prologue: fill up to STAGES stages.
    if (tid == 0) {
        const int pro = myn < STAGES ? myn : STAGES;
        for (int j = 0; j < pro; j++) {
            const size_t off = (size_t)(bid + (size_t)j * grid) * CHUNK_BYTES;
            const uint32_t d  = smem_u32(sm) + j * STAGE_BYTES;
            const uint32_t mb = smem_u32(&mbar[j]);
            mbar_expect_tx(mb, STAGE_BYTES);
            bulk_g2s(d,               ga + off, CHUNK_BYTES, mb);
            bulk_g2s(d + CHUNK_BYTES, gb + off, CHUNK_BYTES, mb);
        }
    }

    // Thread t handles local floats [12t, 12t+12): starts at 12t == 0 mod 3,
    // so the float4 weight pattern is compile-time fixed (same as R8 groups).
    float s0 = 0.0f, s1 = 0.0f, s2 = 0.0f;
    const int b4 = 3 * tid;

    for (int i = 0; i < myn; i++) {
        const int slot = i % STAGES;
        const uint32_t parity = (uint32_t)((i / STAGES) & 1);
        mbar_wait(smem_u32(&mbar[slot]), parity);

        const float4* ca = (const float4*)(sm + slot * STAGE_BYTES);
        const float4* cb = (const float4*)(sm + slot * STAGE_BYTES + CHUNK_BYTES);
        float4 a0 = ca[b4], a1 = ca[b4 + 1], a2 = ca[b4 + 2];
        float4 b0 = cb[b4], b1 = cb[b4 + 1], b2 = cb[b4 + 2];

        s0 += W0 * fabsf(a0.x - b0.x) + W1 * fabsf(a0.y - b0.y)
            + W2 * fabsf(a0.z - b0.z) + W0 * fabsf(a0.w - b0.w);
        s1 += W1 * fabsf(a1.x - b1.x) + W2 * fabsf(a1.y - b1.y)
            + W0 * fabsf(a1.z - b1.z) + W1 * fabsf(a1.w - b1.w);
        s2 += W2 * fabsf(a2.x - b2.x) + W0 * fabsf(a2.y - b2.y)
            + W1 * fabsf(a2.z - b2.z) + W2 * fabsf(a2.w - b2.w);

        __syncthreads();   // all lanes done reading this stage

        if (tid == 0 && i + STAGES < myn) {
            const size_t off = (size_t)(bid + (size_t)(i + STAGES) * grid) * CHUNK_BYTES;
            const uint32_t d  = smem_u32(sm) + slot * STAGE_BYTES;
            const uint32_t mb = smem_u32(&mbar[slot]);
            mbar_expect_tx(mb, STAGE_BYTES);
            bulk_g2s(d,               ga + off, CHUNK_BYTES, mb);
            bulk_g2s(d + CHUNK_BYTES, gb + off, CHUNK_BYTES, mb);
        }
    }

    float s = s0 + s1 + s2;

    // Scalar tail for floats beyond nchunks*CHUNK_FLOATS (empty for this shape).
    {
        const float w3[3] = {W0, W1, W2};
        for (int i = nchunks * CHUNK_FLOATS + bid * THREADS + tid;
             i < n_total; i += grid * THREADS)
            s += w3[i % 3] * fabsf(fa[i] - fb[i]);
    }

    // Warp reduction
    #pragma unroll
    for (int off = 16; off > 0; off >>= 1)
        s += __shfl_xor_sync(0xFFFFFFFFu, s, off);

    const int lane = tid & 31, wid = tid >> 5;
    if (lane == 0) warp_sums[wid] = s;
    __syncthreads();

    if (wid == 0) {
        s = (lane < THREADS / 32) ? warp_sums[lane] : 0.0f;
        #pragma unroll
        for (int off = 2; off > 0; off >>= 1)
            s += __shfl_xor_sync(0xFFFFFFFFu, s, off);
        if (lane == 0)
            atomicAdd(out, s * inv_n);
    }
}

extern "C" void kernel_launch(void* const* d_in, const int* in_sizes, int n_in,
                              void* d_out, int out_size)
{
    const float* t1 = (const float*)d_in[0];
    const float* t2 = (const float*)d_in[1];
    float* out = (float*)d_out;

    const int n_total  = in_sizes[0];                 // 12,582,912 floats
    const int nchunks  = n_total / CHUNK_FLOATS;      // 8192
    const int n_sample = n_total / 3;                 // 4,194,304
    const float inv_n  = 1.0f / (float)n_sample;

    wmae_zero_kernel<<<1, 1>>>(out);

    int blocks = 6 * 148;                             // 6 CTAs/SM (36KB smem each)
    if (blocks > nchunks && nchunks > 0) blocks = nchunks;
    if (blocks < 1) blocks = 1;

    wmae_kernel<<<blocks, THREADS>>>(
        (const char*)t1, (const char*)t2,
        t1, t2, out, nchunks, n_total, inv_n);
}